// round 9
// baseline (speedup 1.0000x reference)
#include <cuda_runtime.h>
#include <cstdint>

// RVQ: B=32, T=4096, MEL=128, D=64, K=128. N = 131072 tokens.
// recon = dec0[i0] + dec1[i1]; i0/i1 from fused scores GEMM + Gram fold.

#define NTOK   (32 * 4096)
#define NTILE  (NTOK / 64)
#define NTHR   256

// ---- precomputed tables (device globals; allocation-free scratch) ----
__device__ __align__(16) float g_twoG[128 * 128]; // 2 * cb0[j] . cb1[k]
__device__ __align__(16) float g_dec0[128 * 128]; // cb0[j] @ w_out^T + b_out
__device__ __align__(16) float g_dec1[128 * 128]; // cb1[j] @ w_out^T
__device__ __align__(16) float g_cT[64 * 256];    // cT[d][k]: k<128 -> cb0[k][d], else cb1[k-128][d]
__device__ __align__(16) float g_wT[128 * 64];    // wT[m][d] = w_in[d][m]
__device__ __align__(16) float g_c0n[128];
__device__ __align__(16) float g_c1n[128];

__device__ __forceinline__ float dot64(const float* __restrict__ a,
                                       const float* __restrict__ b) {
    float s = 0.f;
    const float4* b4 = (const float4*)b;
#pragma unroll
    for (int q = 0; q < 16; ++q) {
        float4 v = b4[q];
        s += a[4*q+0]*v.x + a[4*q+1]*v.y + a[4*q+2]*v.z + a[4*q+3]*v.w;
    }
    return s;
}

__global__ void rvq_precompute(const float* __restrict__ w_in,
                               const float* __restrict__ cb0,
                               const float* __restrict__ cb1,
                               const float* __restrict__ w_out,
                               const float* __restrict__ b_out) {
    __shared__ float c0r[64], c1r[64];
    const int j = blockIdx.x;      // 0..127
    const int t = threadIdx.x;     // 0..255
    if (t < 64)        c0r[t]      = cb0[j * 64 + t];
    else if (t < 128)  c1r[t - 64] = cb1[j * 64 + (t - 64)];
    __syncthreads();

    if (t < 128) {
        g_twoG[j * 128 + t] = 2.f * dot64(c0r, cb1 + t * 64);
        g_dec1[j * 128 + t] = dot64(c1r, w_out + t * 64);
        if (j < 64) {                       // wT: 8192 elems over 64 blocks
            int e = j * 128 + t;            // e = m*64 + d
            g_wT[e] = w_in[(e & 63) * 128 + (e >> 6)];
        }
    } else {
        int m = t - 128;
        g_dec0[j * 128 + m] = dot64(c0r, w_out + m * 64) + b_out[m];
        int e = j * 128 + m;                // cT: e = d*256 + k
        int d = e >> 8, k = e & 255;
        g_cT[e] = (k < 128) ? cb0[k * 64 + d] : cb1[(k - 128) * 64 + d];
    }
    if (t == 0)  { float s = 0.f; for (int d = 0; d < 64; ++d) s += c0r[d]*c0r[d]; g_c0n[j] = s; }
    if (t == 32) { float s = 0.f; for (int d = 0; d < 64; ++d) s += c1r[d]*c1r[d]; g_c1n[j] = s; }
}

// ---- smem layout (floats) ----
// region A [0,12544): phase1 = mel[64][132] (8448) + wT chunk [64][16 f4] (4096)
//                     phase2 = cT half [64][32 f4] (8192)
//                     argmin = pv[64][32] (2048) + pk[64][32] (2048)
// Z [12544,16896): z[64][68]
// i0s [16896,16960)  i1s [16960,17024)
#define OFF_W   8448
#define OFF_Z   12544
#define OFF_I0  16896
#define OFF_I1  16960
#define SMEM_FLOATS 17024
#define SMEM_BYTES  (SMEM_FLOATS * 4)

__global__ void __launch_bounds__(NTHR, 3)
rvq_main(const float* __restrict__ mel, const float* __restrict__ b_in,
         float* __restrict__ out) {
    extern __shared__ float sm[];
    float*  smMel = sm;                       // [64][132]
    float4* smW4  = (float4*)(sm + OFF_W);    // [64 m][16]
    float4* smC4  = (float4*)sm;              // [64 d][32] (phase 2 halves)
    float*  smZ   = sm + OFF_Z;               // [64][68]
    float*  pv    = sm;                       // [64][32] (overlay, after cT half dead)
    int*    pk    = (int*)(sm + 2048);        // [64][32]
    int*    i0s   = (int*)(sm + OFF_I0);
    int*    i1s   = (int*)(sm + OFF_I1);

    const int tid  = threadIdx.x;
    const int tile = blockIdx.x;
    const int lane = tid & 31;
    const int wrp  = tid >> 5;
    const int tok0 = wrp * 8;

    // ---- stage mel (64x128, stride 132) + wT chunk 0 ----
    {
        const float4* mg = (const float4*)(mel + (size_t)tile * (64 * 128));
#pragma unroll
        for (int r = 0; r < 8; ++r) {
            int f = tid + NTHR * r;            // 0..2047 float4
            int tk = f >> 5, m4 = f & 31;
            *(float4*)(smMel + tk * 132 + m4 * 4) = mg[f];
        }
        const float4* wg = (const float4*)g_wT;
#pragma unroll
        for (int r = 0; r < 4; ++r) { int f = tid + NTHR * r; smW4[f] = wg[f]; }
    }
    __syncthreads();

    // ---- phase 1: z = mel @ w_in^T + b_in.  4 tok x 4 d per thread.
    //      mel read coalesced (1 wf per mq) + shfl distribution.
    {
        const int tg  = tid >> 4;         // token group: tokens tg*4..+3
        const int dg  = tid & 15;         // d = dg*4..+3
        const int tg1 = tg & 1;           // token-half within this warp
        float acc[4][4];
        {
            float4 b4 = *(const float4*)(b_in + dg * 4);
#pragma unroll
            for (int i = 0; i < 4; ++i) {
                acc[i][0] = b4.x; acc[i][1] = b4.y; acc[i][2] = b4.z; acc[i][3] = b4.w;
            }
        }
        // coalesced mel address for this lane: token tok0 + (lane>>2), m-offset lane&3
        const float* melc = smMel + (tok0 + (lane >> 2)) * 132 + (lane & 3);
#pragma unroll
        for (int ch = 0; ch < 2; ++ch) {
            if (ch == 1) {
                __syncthreads();          // chunk-0 reads complete
                const float4* wg = (const float4*)g_wT + 1024;
#pragma unroll
                for (int r = 0; r < 4; ++r) { int f = tid + NTHR * r; smW4[f] = wg[f]; }
                __syncthreads();
            }
#pragma unroll 4
            for (int mq = 0; mq < 16; ++mq) {
                // lane holds mel[tok0 + (lane>>2)][ch*64 + mq*4 + (lane&3)]
                float ar = melc[ch * 64 + mq * 4];
#pragma unroll
                for (int mm = 0; mm < 4; ++mm) {
                    float4 w = smW4[(mq * 4 + mm) * 16 + dg];
#pragma unroll
                    for (int i = 0; i < 4; ++i) {
                        float av = __shfl_sync(0xffffffffu, ar, ((tg1 * 4 + i) << 2) | mm);
                        acc[i][0] += av * w.x; acc[i][1] += av * w.y;
                        acc[i][2] += av * w.z; acc[i][3] += av * w.w;
                    }
                }
            }
        }
#pragma unroll
        for (int i = 0; i < 4; ++i)
            *(float4*)(smZ + (tg * 4 + i) * 68 + dg * 4) =
                make_float4(acc[i][0], acc[i][1], acc[i][2], acc[i][3]);
    }
    __syncthreads();   // z ready; region A free

    float a[8][4];
    const float4* cg4 = (const float4*)g_cT;
    // coalesced z address for this lane: token tok0 + (lane>>2), d-offset lane&3
    const float* zc = smZ + (tok0 + (lane >> 2)) * 68 + (lane & 3);

    // =========== pass A: level-0 scores (k = lane*4 + j) ===========
    {
#pragma unroll
        for (int r = 0; r < 8; ++r) {       // stage cT cols [0,128)
            int f = tid + NTHR * r;          // 0..2047
            smC4[f] = cg4[(f >> 5) * 64 + (f & 31)];
        }
    }
    __syncthreads();
#pragma unroll
    for (int t = 0; t < 8; ++t)
#pragma unroll
        for (int j = 0; j < 4; ++j) a[t][j] = 0.f;
#pragma unroll 2
    for (int dq = 0; dq < 16; ++dq) {
        float zr = zc[dq * 4];               // z[tok0+(lane>>2)][dq*4+(lane&3)], 1 wf
#pragma unroll
        for (int dd = 0; dd < 4; ++dd) {
            float4 c = smC4[(dq * 4 + dd) * 32 + lane];
#pragma unroll
            for (int t = 0; t < 8; ++t) {
                float zv = __shfl_sync(0xffffffffu, zr, (t << 2) | dd);
                a[t][0] += zv * c.x; a[t][1] += zv * c.y;
                a[t][2] += zv * c.z; a[t][3] += zv * c.w;
            }
        }
    }
    __syncthreads();   // cT half dead -> pv/pk
    {
        float4 n0 = *(const float4*)(g_c0n + lane * 4);
        float nn[4] = {n0.x, n0.y, n0.z, n0.w};
#pragma unroll
        for (int t = 0; t < 8; ++t) {
            float best = 3.402823466e38f; int bi = 0;
#pragma unroll
            for (int j = 0; j < 4; ++j) {
                float v = nn[j] - 2.f * a[t][j];
                if (v < best) { best = v; bi = lane * 4 + j; }
            }
            pv[(tok0 + t) * 32 + lane] = best;
            pk[(tok0 + t) * 32 + lane] = bi;
        }
    }
    __syncthreads();
    if (tid < 64) {
        float best = pv[tid * 32]; int bi = pk[tid * 32];
#pragma unroll 8
        for (int l = 1; l < 32; ++l) {
            float v = pv[tid * 32 + l];
            if (v < best) { best = v; bi = pk[tid * 32 + l]; }
        }
        i0s[tid] = bi;
    }
    __syncthreads();

    // =========== pass B: level-1 scores + Gram fold ===========
    {
#pragma unroll
        for (int r = 0; r < 8; ++r) {       // stage cT cols [128,256)
            int f = tid + NTHR * r;
            smC4[f] = cg4[(f >> 5) * 64 + 32 + (f & 31)];
        }
    }
    __syncthreads();
#pragma unroll
    for (int t = 0; t < 8; ++t)
#pragma unroll
        for (int j = 0; j < 4; ++j) a[t][j] = 0.f;
#pragma unroll 2
    for (int dq = 0; dq < 16; ++dq) {
        float zr = zc[dq * 4];
#pragma unroll
        for (int dd = 0; dd < 4; ++dd) {
            float4 c = smC4[(dq * 4 + dd) * 32 + lane];
#pragma unroll
            for (int t = 0; t < 8; ++t) {
                float zv = __shfl_sync(0xffffffffu, zr, (t << 2) | dd);
                a[t][0] += zv * c.x; a[t][1] += zv * c.y;
                a[t][2] += zv * c.z; a[t][3] += zv * c.w;
            }
        }
    }
    __syncthreads();   // cT half dead -> pv/pk
    {
        float4 n1 = *(const float4*)(g_c1n + lane * 4);
        float nn[4] = {n1.x, n1.y, n1.z, n1.w};
#pragma unroll
        for (int t = 0; t < 8; ++t) {
            float4 g4 = *(const float4*)(g_twoG + i0s[tok0 + t] * 128 + lane * 4);
            float best = 3.402823466e38f; int bi = 0;
            float vv[4] = {nn[0] - 2.f * a[t][0] + g4.x,
                           nn[1] - 2.f * a[t][1] + g4.y,
                           nn[2] - 2.f * a[t][2] + g4.z,
                           nn[3] - 2.f * a[t][3] + g4.w};
#pragma unroll
            for (int j = 0; j < 4; ++j)
                if (vv[j] < best) { best = vv[j]; bi = lane * 4 + j; }
            pv[(tok0 + t) * 32 + lane] = best;
            pk[(tok0 + t) * 32 + lane] = bi;
        }
    }
    __syncthreads();
    if (tid < 64) {
        float best = pv[tid * 32]; int bi = pk[tid * 32];
#pragma unroll 8
        for (int l = 1; l < 32; ++l) {
            float v = pv[tid * 32 + l];
            if (v < best) { best = v; bi = pk[tid * 32 + l]; }
        }
        i1s[tid] = bi;
    }
    __syncthreads();

    // ---- phase 3: out = dec0[i0] + dec1[i1] (coalesced float4) ----
    {
        const float4* d0 = (const float4*)g_dec0;
        const float4* d1 = (const float4*)g_dec1;
        float4* o4 = (float4*)out + (size_t)tile * 2048;
#pragma unroll
        for (int r = 0; r < 8; ++r) {
            int f = tid + NTHR * r;            // 0..2047
            int tok = f >> 5, m4 = f & 31;
            float4 va = d0[i0s[tok] * 32 + m4];
            float4 vb = d1[i1s[tok] * 32 + m4];
            o4[f] = make_float4(va.x + vb.x, va.y + vb.y, va.z + vb.z, va.w + vb.w);
        }
    }
}

extern "C" void kernel_launch(void* const* d_in, const int* in_sizes, int n_in,
                              void* d_out, int out_size) {
    const float* mel   = (const float*)d_in[0];
    const float* w_in  = (const float*)d_in[1];
    const float* b_in  = (const float*)d_in[2];
    const float* cb0   = (const float*)d_in[3];
    const float* cb1   = (const float*)d_in[4];
    const float* w_out = (const float*)d_in[5];
    const float* b_out = (const float*)d_in[6];
    float* out = (float*)d_out;

    cudaFuncSetAttribute(rvq_main, cudaFuncAttributeMaxDynamicSharedMemorySize, SMEM_BYTES);

    rvq_precompute<<<128, NTHR>>>(w_in, cb0, cb1, w_out, b_out);
    rvq_main<<<NTILE, NTHR, SMEM_BYTES>>>(mel, b_in, out);
}

// round 11
// speedup vs baseline: 1.0761x; 1.0761x over previous
#include <cuda_runtime.h>
#include <cuda_bf16.h>
#include <cstdint>

// RVQ via mma.sync bf16 (6-term error-free split ~ fp32 parity):
// s[tok][k] = mel @ E^T (E = [cb0;cb1] @ w_in, 256x128), argmin w/ Gram fold,
// decode via tables. No sm_103a-only PTX (harness targets compute_103).

#define NTOK   (32 * 4096)
#define TILE_T 128
#define NTILE  (NTOK / TILE_T)   // 1024
#define NTHR   256

// ---- precomputed tables ----
__device__ __align__(16) float g_twoG[128 * 128]; // 2 * cb0[j] . cb1[k]
__device__ __align__(16) float g_dec0[128 * 128]; // cb0[j] @ w_out^T + b_out
__device__ __align__(16) float g_dec1[128 * 128]; // cb1[j] @ w_out^T
__device__ __align__(16) float g_adj0[128];       // ||c0||^2 - 2 b.c0
__device__ __align__(16) float g_adj1[128];       // ||c1||^2 - 2 b.c1
// B fragment images, mma.m16n8k16 layout, 3 bf16 splits:
// idx = ((pass*8 + kst)*16 + nf)*32 + lane
// g_B12[idx] = uint4{ b0_s1, b1_s1, b0_s2, b1_s2 };  g_B3[idx] = uint2{ b0_s3, b1_s3 }
__device__ __align__(16) uint32_t g_B12[2 * 8 * 16 * 32 * 4]; // 128KB
__device__ __align__(16) uint32_t g_B3 [2 * 8 * 16 * 32 * 2]; // 64KB

__device__ __forceinline__ float dot64(const float* __restrict__ a,
                                       const float* __restrict__ b) {
    float s = 0.f;
    const float4* b4 = (const float4*)b;
#pragma unroll
    for (int q = 0; q < 16; ++q) {
        float4 v = b4[q];
        s += a[4*q+0]*v.x + a[4*q+1]*v.y + a[4*q+2]*v.z + a[4*q+3]*v.w;
    }
    return s;
}

// write one E value (3 bf16 splits) into the packed fragment images
__device__ __forceinline__ void write_B(int pass, int n, int k, float v) {
    const int nf = n >> 3, lg = n & 7;
    const int kst = k >> 4, kk = k & 15;
    const int kh = kk >> 3;          // b0 vs b1 reg
    const int lc = (kk & 7) >> 1;    // lane&3
    const int hl = kk & 1;           // lo/hi bf16 in reg
    const int lane = lg * 4 + lc;
    const int idx = ((pass * 8 + kst) * 16 + nf) * 32 + lane;
    unsigned short* B12 = (unsigned short*)g_B12;
    unsigned short* B3  = (unsigned short*)g_B3;
#pragma unroll
    for (int s = 0; s < 3; ++s) {
        __nv_bfloat16 h = __float2bfloat16_rn(v);
        unsigned short us = __bfloat16_as_ushort(h);
        if (s < 2) B12[(idx * 4 + 2 * s + kh) * 2 + hl] = us;
        else       B3 [(idx * 2 + kh) * 2 + hl] = us;
        v -= __bfloat162float(h);
    }
}

__global__ void rvq_precompute(const float* __restrict__ w_in,
                               const float* __restrict__ b_in,
                               const float* __restrict__ cb0,
                               const float* __restrict__ cb1,
                               const float* __restrict__ w_out,
                               const float* __restrict__ b_out) {
    __shared__ float c0r[64], c1r[64];
    const int j = blockIdx.x;      // 0..127
    const int t = threadIdx.x;     // 0..255
    if (t < 64)        c0r[t]      = cb0[j * 64 + t];
    else if (t < 128)  c1r[t - 64] = cb1[j * 64 + (t - 64)];
    __syncthreads();

    if (t < 128) {
        g_twoG[j * 128 + t] = 2.f * dot64(c0r, cb1 + t * 64);
        g_dec1[j * 128 + t] = dot64(c1r, w_out + t * 64);
        const int m = t;
        float e0 = 0.f, e1 = 0.f;
#pragma unroll 8
        for (int d = 0; d < 64; ++d) {
            float w = w_in[d * 128 + m];
            e0 += c0r[d] * w; e1 += c1r[d] * w;
        }
        write_B(0, j, m, e0);     // codes 0..127  (cb0 level)
        write_B(1, j, m, e1);     // codes 128..255 (cb1 level)
    } else {
        int m = t - 128;
        g_dec0[j * 128 + m] = dot64(c0r, w_out + m * 64) + b_out[m];
    }
    if (t == 0) {
        float n = 0.f, db = 0.f;
        for (int d = 0; d < 64; ++d) { n += c0r[d]*c0r[d]; db += b_in[d]*c0r[d]; }
        g_adj0[j] = n - 2.f * db;
    }
    if (t == 32) {
        float n = 0.f, db = 0.f;
        for (int d = 0; d < 64; ++d) { n += c1r[d]*c1r[d]; db += b_in[d]*c1r[d]; }
        g_adj1[j] = n - 2.f * db;
    }
}

__device__ __forceinline__ void mma_bf16(float* d, const uint32_t* a,
                                         uint32_t b0, uint32_t b1) {
    asm volatile(
        "mma.sync.aligned.m16n8k16.row.col.f32.bf16.bf16.f32 "
        "{%0,%1,%2,%3}, {%4,%5,%6,%7}, {%8,%9}, {%0,%1,%2,%3};\n"
        : "+f"(d[0]), "+f"(d[1]), "+f"(d[2]), "+f"(d[3])
        : "r"(a[0]), "r"(a[1]), "r"(a[2]), "r"(a[3]), "r"(b0), "r"(b1));
}

// smem bytes: A (mel fp32 [128][132]) [0,67584)
//             B12 [67584,133120)  B3 [133120,165888)
//             scores overlay [128][132] at 67584 (B region, time-shared)
//             i0s @165888, i1s @166400
#define OFF_B12 67584
#define OFF_B3  133120
#define OFF_S   67584
#define OFF_I0  165888
#define OFF_I1  166400
#define SMEM_BYTES 166912

__global__ void __launch_bounds__(NTHR, 1)
rvq_main(const float* __restrict__ mel, float* __restrict__ out) {
    extern __shared__ __align__(16) uint8_t smem[];
    float* smA   = (float*)smem;                    // [128][132]
    uint4* smB12 = (uint4*)(smem + OFF_B12);        // [8][16][32]
    uint2* smB3  = (uint2*)(smem + OFF_B3);         // [8][16][32]
    float* smS   = (float*)(smem + OFF_S);          // [128][132] overlay
    int*   i0s   = (int*)(smem + OFF_I0);
    int*   i1s   = (int*)(smem + OFF_I1);

    const int tid  = threadIdx.x;
    const int lane = tid & 31;
    const int wid  = tid >> 5;
    const int tile = blockIdx.x;
    const int g    = lane >> 2;    // mma group id
    const int tt   = lane & 3;     // thread-in-group

    // ---- stage mel (128 tok x 128, pad 132) ----
    {
        const float4* mg = (const float4*)mel + (size_t)tile * 4096;
#pragma unroll
        for (int r = 0; r < 16; ++r) {
            int f = tid + NTHR * r;            // 0..4095 float4
            int tok = f >> 5, m4 = f & 31;
            *(float4*)(smA + tok * 132 + m4 * 4) = mg[f];
        }
    }

    const int mw = wid & 3, nw = wid >> 2;
    const int tokB = mw * 32, nfB = nw * 8;

#pragma unroll 1
    for (int ch = 0; ch < 2; ++ch) {
        // ---- stage B fragment images for this pass ----
        {
            const uint4* gb12 = (const uint4*)g_B12 + ch * 4096;
#pragma unroll
            for (int r = 0; r < 16; ++r) smB12[tid + NTHR * r] = gb12[tid + NTHR * r];
            const uint4* gb3 = (const uint4*)g_B3 + ch * 2048;
            uint4* sb3 = (uint4*)smB3;
#pragma unroll
            for (int r = 0; r < 8; ++r) sb3[tid + NTHR * r] = gb3[tid + NTHR * r];
        }
        __syncthreads();

        // ---- GEMM: warp = 32 tok x 64 codes, K=128 (8 ksteps), 6 split-terms
        float d[2][8][4];
#pragma unroll
        for (int mf = 0; mf < 2; ++mf)
#pragma unroll
            for (int nf = 0; nf < 8; ++nf)
#pragma unroll
                for (int q = 0; q < 4; ++q) d[mf][nf][q] = 0.f;

#pragma unroll 1
        for (int kst = 0; kst < 8; ++kst) {
            uint32_t A[2][3][4];
#pragma unroll
            for (int mf = 0; mf < 2; ++mf) {
                const int r0 = tokB + mf * 16 + g;
                const int c0 = kst * 16 + tt * 2;
                float2 e[4];
                e[0] = *(const float2*)(smA + r0 * 132 + c0);
                e[1] = *(const float2*)(smA + (r0 + 8) * 132 + c0);
                e[2] = *(const float2*)(smA + r0 * 132 + c0 + 8);
                e[3] = *(const float2*)(smA + (r0 + 8) * 132 + c0 + 8);
#pragma unroll
                for (int p = 0; p < 4; ++p) {
                    float lo = e[p].x, hi = e[p].y;
#pragma unroll
                    for (int s = 0; s < 3; ++s) {
                        __nv_bfloat16 bl = __float2bfloat16_rn(lo);
                        __nv_bfloat16 bh = __float2bfloat16_rn(hi);
                        A[mf][s][p] = (uint32_t)__bfloat16_as_ushort(bl)
                                    | ((uint32_t)__bfloat16_as_ushort(bh) << 16);
                        lo -= __bfloat162float(bl);
                        hi -= __bfloat162float(bh);
                    }
                }
            }
#pragma unroll
            for (int nf = 0; nf < 8; ++nf) {
                const int bidx = (kst * 16 + nfB + nf) * 32 + lane;
                uint4 b12 = smB12[bidx];
                uint2 b3  = smB3[bidx];
#pragma unroll
                for (int mf = 0; mf < 2; ++mf) {
                    mma_bf16(d[mf][nf], A[mf][0], b12.x, b12.y);  // a1*b1
                    mma_bf16(d[mf][nf], A[mf][0], b12.z, b12.w);  // a1*b2
                    mma_bf16(d[mf][nf], A[mf][1], b12.x, b12.y);  // a2*b1
                    mma_bf16(d[mf][nf], A[mf][1], b12.z, b12.w);  // a2*b2
                    mma_bf16(d[mf][nf], A[mf][0], b3.x,  b3.y);   // a1*b3
                    mma_bf16(d[mf][nf], A[mf][2], b12.x, b12.y);  // a3*b1
                }
            }
        }
        __syncthreads();   // B region dead -> scores overlay

        // ---- dump scores to smS[tok][code] ----
#pragma unroll
        for (int mf = 0; mf < 2; ++mf) {
            const int r0 = tokB + mf * 16 + g;
#pragma unroll
            for (int nf = 0; nf < 8; ++nf) {
                const int c = (nfB + nf) * 8 + tt * 2;
                *(float2*)(smS + r0 * 132 + c)       = make_float2(d[mf][nf][0], d[mf][nf][1]);
                *(float2*)(smS + (r0 + 8) * 132 + c) = make_float2(d[mf][nf][2], d[mf][nf][3]);
            }
        }
        __syncthreads();

        // ---- per-token argmin (ascending k, first-min tie-break) ----
        if (tid < 128) {
            const float4* srow = (const float4*)(smS + tid * 132);
            float best = 3.402823466e38f; int bi = 0;
            if (ch == 0) {
#pragma unroll 4
                for (int q = 0; q < 32; ++q) {
                    float4 s4 = srow[q];
                    float4 a4 = ((const float4*)g_adj0)[q];
                    float v0 = a4.x - 2.f * s4.x, v1 = a4.y - 2.f * s4.y;
                    float v2 = a4.z - 2.f * s4.z, v3 = a4.w - 2.f * s4.w;
                    if (v0 < best) { best = v0; bi = 4*q;   }
                    if (v1 < best) { best = v1; bi = 4*q+1; }
                    if (v2 < best) { best = v2; bi = 4*q+2; }
                    if (v3 < best) { best = v3; bi = 4*q+3; }
                }
                i0s[tid] = bi;
            } else {
                const float4* grow = (const float4*)(g_twoG + i0s[tid] * 128);
#pragma unroll 4
                for (int q = 0; q < 32; ++q) {
                    float4 s4 = srow[q];
                    float4 a4 = ((const float4*)g_adj1)[q];
                    float4 g4 = grow[q];
                    float v0 = a4.x - 2.f * s4.x + g4.x, v1 = a4.y - 2.f * s4.y + g4.y;
                    float v2 = a4.z - 2.f * s4.z + g4.z, v3 = a4.w - 2.f * s4.w + g4.w;
                    if (v0 < best) { best = v0; bi = 4*q;   }
                    if (v1 < best) { best = v1; bi = 4*q+1; }
                    if (v2 < best) { best = v2; bi = 4*q+2; }
                    if (v3 < best) { best = v3; bi = 4*q+3; }
                }
                i1s[tid] = bi;
            }
        }
        __syncthreads();
    }

    // ---- decode: out = dec0[i0] + dec1[i1] (coalesced float4) ----
    {
        const float4* d0 = (const float4*)g_dec0;
        const float4* d1 = (const float4*)g_dec1;
        float4* o4 = (float4*)out + (size_t)tile * 4096;
#pragma unroll
        for (int r = 0; r < 16; ++r) {
            int f = tid + NTHR * r;            // 0..4095
            int tok = f >> 5, m4 = f & 31;
            float4 va = d0[i0s[tok] * 32 + m4];
            float4 vb = d1[i1s[tok] * 32 + m4];
            o4[f] = make_float4(va.x + vb.x, va.y + vb.y, va.z + vb.z, va.w + vb.w);
        }
    }
}

extern "C" void kernel_launch(void* const* d_in, const int* in_sizes, int n_in,
                              void* d_out, int out_size) {
    const float* mel   = (const float*)d_in[0];
    const float* w_in  = (const float*)d_in[1];
    const float* b_in  = (const float*)d_in[2];
    const float* cb0   = (const float*)d_in[3];
    const float* cb1   = (const float*)d_in[4];
    const float* w_out = (const float*)d_in[5];
    const float* b_out = (const float*)d_in[6];
    float* out = (float*)d_out;

    cudaFuncSetAttribute(rvq_main, cudaFuncAttributeMaxDynamicSharedMemorySize, SMEM_BYTES);

    rvq_precompute<<<128, NTHR>>>(w_in, b_in, cb0, cb1, w_out, b_out);
    rvq_main<<<NTILE, NTHR, SMEM_BYTES>>>(mel, out);
}